// round 1
// baseline (speedup 1.0000x reference)
#include <cuda_runtime.h>
#include <cstdint>

#define S 256
#define E 64
#define KNB 20
#define NTHREADS 256
#define NWARPS 8

// shared memory layout (in floats)
#define XS_OFF   0        // 16384 floats: Xs[e][j], e-major stride 256 (reused as key scratch)
#define SROW_OFF 16384    // 2048: per-warp normalized-sims row buffer
#define TW_OFF   18432    // 256
#define IW_OFF   18688    // 256
#define RED_OFF  18944    // 64 floats (8B aligned) reduction scratch
#define SMEM_FLOATS 19008
#define SMEM_BYTES (SMEM_FLOATS * 4)

typedef unsigned long long ull;

__global__ __launch_bounds__(NTHREADS)
void ugc_kernel(const float* __restrict__ item,
                const float* __restrict__ tsg,
                const float* __restrict__ iwg,
                const float* __restrict__ gW1,
                const float* __restrict__ gb1,
                const float* __restrict__ gW2,
                const float* __restrict__ gb2,
                float* __restrict__ out)
{
    extern __shared__ float sm[];
    float* Xs    = sm + XS_OFF;
    float* srow  = sm + SROW_OFF;
    float* s_tw  = sm + TW_OFF;
    float* s_iw  = sm + IW_OFF;
    float* s_red = sm + RED_OFF;

    const int b   = blockIdx.x;
    const int tid = threadIdx.x;
    const int w   = tid >> 5;
    const int l   = tid & 31;

    // ---- load MLP weights into registers (small, broadcast, L1-resident) ----
    float a1[16], a2[16], a3[16], rb1[16], rw2[16];
    #pragma unroll
    for (int k = 0; k < 16; k++) {
        a1[k]  = gW1[k];        // W1[0][k] * sims
        a2[k]  = gW1[16 + k];   // W1[1][k] * tdm
        a3[k]  = gW1[32 + k];   // W1[2][k] * iw
        rb1[k] = gb1[k];
        rw2[k] = gW2[k];
    }
    const float b2v = gb2[0];

    // ---- timestamps max -> temporal weights; interaction weights ----
    const float tsv = tsg[b * S + tid];
    float v = tsv;
    #pragma unroll
    for (int o = 16; o > 0; o >>= 1) v = fmaxf(v, __shfl_xor_sync(0xffffffffu, v, o));
    if (l == 0) s_red[w] = v;
    __syncthreads();
    float tmax = s_red[0];
    #pragma unroll
    for (int r = 1; r < NWARPS; r++) tmax = fmaxf(tmax, s_red[r]);
    const float LN095 = -0.05129329438755058f;      // ln(0.95)
    s_tw[tid] = __expf(LN095 * (tmax - tsv));       // 0.95^(tmax - ts)
    s_iw[tid] = iwg[b * S + tid];

    // ---- stage X transposed into SMEM: Xs[e*256 + j] = X[j][e] ----
    const float* Xg = item + (size_t)b * (S * E);
    #pragma unroll 4
    for (int idx = tid; idx < S * E; idx += NTHREADS) {
        int e = idx >> 8;
        int j = idx & 255;
        Xs[idx] = Xg[j * E + e];
    }
    __syncthreads();

    // ---- per-thread top-K (sorted ascending register list of packed keys) ----
    ull best[KNB];
    #pragma unroll
    for (int n = 0; n < KNB; n++) best[n] = 0ull;
    ull bmin = 0ull;

    // ---- main loop: each warp handles rows i = blk*8 + w ----
    for (int blk = 0; blk < 32; blk++) {
        const int i = blk * 8 + w;

        // full-row dot products (needed for row norm): lane covers j = 4l..4l+3, 128+4l..+3
        float d0 = 0.f, d1 = 0.f, d2 = 0.f, d3 = 0.f;
        float d4 = 0.f, d5 = 0.f, d6 = 0.f, d7 = 0.f;
        #pragma unroll 8
        for (int e = 0; e < E; e++) {
            const float* base = Xs + e * S;
            float xi  = base[i];                                   // broadcast
            float4 A  = *(const float4*)(base + 4 * l);            // conflict-free
            float4 Bv = *(const float4*)(base + 128 + 4 * l);
            d0 = fmaf(xi, A.x,  d0); d1 = fmaf(xi, A.y,  d1);
            d2 = fmaf(xi, A.z,  d2); d3 = fmaf(xi, A.w,  d3);
            d4 = fmaf(xi, Bv.x, d4); d5 = fmaf(xi, Bv.y, d5);
            d6 = fmaf(xi, Bv.z, d6); d7 = fmaf(xi, Bv.w, d7);
        }

        // row norm over ALL 256 columns (intra-warp only)
        float nsq = d0*d0 + d1*d1 + d2*d2 + d3*d3 + d4*d4 + d5*d5 + d6*d6 + d7*d7;
        #pragma unroll
        for (int o = 16; o > 0; o >>= 1) nsq += __shfl_xor_sync(0xffffffffu, nsq, o);
        const float inv = 1.0f / fmaxf(sqrtf(nsq), 1e-12f);

        // stash normalized row so MLP lanes can remap densely over j > i
        float* rb = srow + w * S;
        *(float4*)(rb + 4 * l)       = make_float4(d0*inv, d1*inv, d2*inv, d3*inv);
        *(float4*)(rb + 128 + 4 * l) = make_float4(d4*inv, d5*inv, d6*inv, d7*inv);
        __syncwarp();

        const float twi = s_tw[i];
        const float wvi = s_iw[i];
        float rbase[16];
        #pragma unroll
        for (int k = 0; k < 16; k++) rbase[k] = fmaf(a3[k], wvi, rb1[k]);

        const int flatbase = i << 8;
        for (int j = i + 1 + l; j < S; j += 32) {   // dense triangular mapping
            float s = rb[j];
            float t = twi * s_tw[j];
            float acc = b2v;
            #pragma unroll
            for (int k = 0; k < 16; k++) {
                float pre = fmaf(a1[k], s, fmaf(a2[k], t, rbase[k]));
                acc = fmaf(fmaxf(pre, 0.0f), rw2[k], acc);
            }
            float val = __fdividef(1.0f, 1.0f + __expf(-acc));   // sigmoid
            if (val > 0.1f) {
                // key: value-major, then smaller flat index wins (jax top_k tie-break)
                ull key = ((ull)__float_as_uint(val) << 32)
                        | (ull)(0xffffffffu - (unsigned)(flatbase + j));
                if (key > bmin) {
                    best[0] = key;            // replace min, one bubble pass re-sorts
                    #pragma unroll
                    for (int n = 0; n < KNB - 1; n++) {
                        ull x = best[n], y = best[n + 1];
                        ull lo = (x < y) ? x : y;
                        ull hi = (x < y) ? y : x;
                        best[n] = lo; best[n + 1] = hi;
                    }
                    bmin = best[0];
                }
            }
        }
        __syncwarp();
    }

    // ---- merge 256 per-thread top-20 lists -> global top-20 (descending) ----
    __syncthreads();
    ull* wred = (ull*)s_red;
    float* oSrc = out;
    float* oDst = out + S * KNB;        // 5120
    float* oW   = out + 2 * S * KNB;    // 10240

    for (int r = 0; r < KNB; r++) {
        ull m = 0ull;
        #pragma unroll
        for (int n = 0; n < KNB; n++) m = (best[n] > m) ? best[n] : m;
        #pragma unroll
        for (int o = 16; o > 0; o >>= 1) {
            ull other = __shfl_xor_sync(0xffffffffu, m, o);
            m = (other > m) ? other : m;
        }
        if (l == 0) wred[w] = m;
        __syncthreads();
        ull g = wred[0];
        #pragma unroll
        for (int q = 1; q < NWARPS; q++) { ull o2 = wred[q]; g = (o2 > g) ? o2 : g; }

        if (g != 0ull) {
            #pragma unroll
            for (int n = 0; n < KNB; n++) if (best[n] == g) best[n] = 0ull;  // unique owner
        }
        if (tid == 0) {
            int slot = b * KNB + r;
            if (g != 0ull) {
                float    val  = __uint_as_float((unsigned)(g >> 32));
                unsigned flat = 0xffffffffu - (unsigned)(g & 0xffffffffu);
                int ii = flat >> 8, jj = flat & 255;
                oSrc[slot] = (float)(b * S + ii);
                oDst[slot] = (float)(b * S + jj);
                oW[slot]   = val;
            } else {
                oSrc[slot] = 0.0f; oDst[slot] = 0.0f; oW[slot] = 0.0f;
            }
        }
        __syncthreads();
    }
}

extern "C" void kernel_launch(void* const* d_in, const int* in_sizes, int n_in,
                              void* d_out, int out_size)
{
    // metadata order: user_embeddings(unused), item_embeddings, timestamps,
    // interaction_weights, W1, b1, W2, b2, k_neighbors(=20, hardcoded)
    const float* item = (const float*)d_in[1];
    const float* tsg  = (const float*)d_in[2];
    const float* iwg  = (const float*)d_in[3];
    const float* W1   = (const float*)d_in[4];
    const float* b1   = (const float*)d_in[5];
    const float* W2   = (const float*)d_in[6];
    const float* b2   = (const float*)d_in[7];
    float* out = (float*)d_out;

    cudaFuncSetAttribute(ugc_kernel, cudaFuncAttributeMaxDynamicSharedMemorySize, SMEM_BYTES);
    ugc_kernel<<<S, NTHREADS, SMEM_BYTES>>>(item, tsg, iwg, W1, b1, W2, b2, out);
}

// round 2
// speedup vs baseline: 1.3917x; 1.3917x over previous
#include <cuda_runtime.h>
#include <cstdint>

#define S 256
#define E 64
#define KNB 20
#define NTHREADS 256
#define NWARPS 8

// shared memory layout (in floats)
#define XS_OFF   0        // 16384: Xs[e][j], e-major stride 256
#define SROW_OFF 16384    // 8192: per-warp 4 normalized-sims row buffers
#define TW_OFF   24576    // 256
#define IW_OFF   24832    // 256
#define RED_OFF  25088    // 64 (8B aligned) reduction scratch
#define WT_OFF   25152    // 96: a1,a2,a3,b1,w2,b2
#define SMEM_FLOATS 25248
#define SMEM_BYTES (SMEM_FLOATS * 4)

typedef unsigned long long ull;

__global__ __launch_bounds__(NTHREADS, 2)
void ugc_kernel(const float* __restrict__ item,
                const float* __restrict__ tsg,
                const float* __restrict__ iwg,
                const float* __restrict__ gW1,
                const float* __restrict__ gb1,
                const float* __restrict__ gW2,
                const float* __restrict__ gb2,
                float* __restrict__ out)
{
    extern __shared__ float sm[];
    float* Xs    = sm + XS_OFF;
    float* srow  = sm + SROW_OFF;
    float* s_tw  = sm + TW_OFF;
    float* s_iw  = sm + IW_OFF;
    float* s_red = sm + RED_OFF;
    float* s_wt  = sm + WT_OFF;

    const int b   = blockIdx.x;
    const int tid = threadIdx.x;
    const int w   = tid >> 5;
    const int l   = tid & 31;

    // ---- stage MLP weights into smem (tiny) ----
    if (tid < 16) {
        s_wt[tid]      = gW1[tid];        // a1
        s_wt[16 + tid] = gW1[16 + tid];   // a2
        s_wt[32 + tid] = gW1[32 + tid];   // a3
        s_wt[48 + tid] = gb1[tid];        // b1
        s_wt[64 + tid] = gW2[tid];        // w2
    }
    if (tid == 0) s_wt[80] = gb2[0];

    // ---- timestamps max -> temporal weights; interaction weights ----
    const float tsv = tsg[b * S + tid];
    float v = tsv;
    #pragma unroll
    for (int o = 16; o > 0; o >>= 1) v = fmaxf(v, __shfl_xor_sync(0xffffffffu, v, o));
    if (l == 0) s_red[w] = v;
    __syncthreads();
    float tmax = s_red[0];
    #pragma unroll
    for (int r = 1; r < NWARPS; r++) tmax = fmaxf(tmax, s_red[r]);
    const float LN095 = -0.05129329438755058f;      // ln(0.95)
    s_tw[tid] = __expf(LN095 * (tmax - tsv));       // 0.95^(tmax - ts)
    s_iw[tid] = iwg[b * S + tid];

    // ---- stage X transposed into SMEM: Xs[e*256 + j] = X[j][e] ----
    const float* Xg = item + (size_t)b * (S * E);
    #pragma unroll 4
    for (int idx = tid; idx < S * E; idx += NTHREADS) {
        int e = idx >> 8;
        int j = idx & 255;
        Xs[idx] = Xg[j * E + e];
    }
    __syncthreads();

    // ---- per-thread top-K (sorted ascending register list of packed keys) ----
    ull best[KNB];
    #pragma unroll
    for (int n = 0; n < KNB; n++) best[n] = 0ull;
    ull bmin = 0ull;

    // ---- main loop: 8 passes, each warp owns 4 rows {2u, 2u+1, 254-2u, 255-2u} ----
    for (int pass = 0; pass < 8; pass++) {
        const int u  = pass * NWARPS + w;          // 0..63
        const int r0 = 2 * u;
        const int r1 = 2 * u + 1;
        const int r2 = 254 - 2 * u;
        const int r3 = 255 - 2 * u;

        // 4x256 gram block: 32 accumulators, j-loads amortized over 4 rows
        float a00=0,a01=0,a02=0,a03=0,a04=0,a05=0,a06=0,a07=0;
        float a10=0,a11=0,a12=0,a13=0,a14=0,a15=0,a16=0,a17=0;
        float a20=0,a21=0,a22=0,a23=0,a24=0,a25=0,a26=0,a27=0;
        float a30=0,a31=0,a32=0,a33=0,a34=0,a35=0,a36=0,a37=0;

        const float* bp = Xs;
        #pragma unroll 8
        for (int e = 0; e < E; e++) {
            float4 A  = *(const float4*)(bp + 4 * l);
            float4 Bv = *(const float4*)(bp + 128 + 4 * l);
            float x0 = bp[r0], x1 = bp[r1], x2 = bp[r2], x3 = bp[r3];  // broadcasts
            a00=fmaf(x0,A.x,a00); a01=fmaf(x0,A.y,a01); a02=fmaf(x0,A.z,a02); a03=fmaf(x0,A.w,a03);
            a04=fmaf(x0,Bv.x,a04);a05=fmaf(x0,Bv.y,a05);a06=fmaf(x0,Bv.z,a06);a07=fmaf(x0,Bv.w,a07);
            a10=fmaf(x1,A.x,a10); a11=fmaf(x1,A.y,a11); a12=fmaf(x1,A.z,a12); a13=fmaf(x1,A.w,a13);
            a14=fmaf(x1,Bv.x,a14);a15=fmaf(x1,Bv.y,a15);a16=fmaf(x1,Bv.z,a16);a17=fmaf(x1,Bv.w,a17);
            a20=fmaf(x2,A.x,a20); a21=fmaf(x2,A.y,a21); a22=fmaf(x2,A.z,a22); a23=fmaf(x2,A.w,a23);
            a24=fmaf(x2,Bv.x,a24);a25=fmaf(x2,Bv.y,a25);a26=fmaf(x2,Bv.z,a26);a27=fmaf(x2,Bv.w,a27);
            a30=fmaf(x3,A.x,a30); a31=fmaf(x3,A.y,a31); a32=fmaf(x3,A.z,a32); a33=fmaf(x3,A.w,a33);
            a34=fmaf(x3,Bv.x,a34);a35=fmaf(x3,Bv.y,a35);a36=fmaf(x3,Bv.z,a36);a37=fmaf(x3,Bv.w,a37);
            bp += S;
        }

        // row norms (over ALL 256 cols) + normalized store to srow
        #define DO_NORM(A0,A1,A2,A3,A4,A5,A6,A7,Q)                                       \
        {                                                                                \
            float nsq = A0*A0+A1*A1+A2*A2+A3*A3+A4*A4+A5*A5+A6*A6+A7*A7;                 \
            _Pragma("unroll")                                                            \
            for (int o = 16; o > 0; o >>= 1) nsq += __shfl_xor_sync(0xffffffffu,nsq,o);  \
            float inv = 1.0f / fmaxf(sqrtf(nsq), 1e-12f);                                \
            float* rb_ = srow + ((w << 2) + (Q)) * S;                                    \
            *(float4*)(rb_ + 4*l)       = make_float4(A0*inv, A1*inv, A2*inv, A3*inv);   \
            *(float4*)(rb_ + 128 + 4*l) = make_float4(A4*inv, A5*inv, A6*inv, A7*inv);   \
        }
        DO_NORM(a00,a01,a02,a03,a04,a05,a06,a07,0)
        DO_NORM(a10,a11,a12,a13,a14,a15,a16,a17,1)
        DO_NORM(a20,a21,a22,a23,a24,a25,a26,a27,2)
        DO_NORM(a30,a31,a32,a33,a34,a35,a36,a37,3)
        #undef DO_NORM
        __syncwarp();

        // ---- MLP + threshold + top-k over this warp's 4 rows ----
        float c1[16], c2[16], cw2[16];
        #pragma unroll
        for (int k = 0; k < 16; k++) {
            c1[k]  = s_wt[k];
            c2[k]  = s_wt[16 + k];
            cw2[k] = s_wt[64 + k];
        }
        const float b2v = s_wt[80];

        #pragma unroll
        for (int q = 0; q < 4; q++) {
            const int i = (q == 0) ? r0 : (q == 1) ? r1 : (q == 2) ? r2 : r3;
            const float* rb = srow + ((w << 2) + q) * S;
            const float twi = s_tw[i];
            const float wvi = s_iw[i];
            float rbase[16];
            #pragma unroll
            for (int k = 0; k < 16; k++)
                rbase[k] = fmaf(s_wt[32 + k], wvi, s_wt[48 + k]);   // a3*iw + b1

            const int flatbase = i << 8;
            for (int j = i + 1 + l; j < S; j += 32) {
                float s = rb[j];
                float t = twi * s_tw[j];
                float acc = b2v;
                #pragma unroll
                for (int k = 0; k < 16; k++) {
                    float pre = fmaf(c1[k], s, fmaf(c2[k], t, rbase[k]));
                    acc = fmaf(fmaxf(pre, 0.0f), cw2[k], acc);
                }
                float val = __fdividef(1.0f, 1.0f + __expf(-acc));   // sigmoid
                if (val > 0.1f) {
                    ull key = ((ull)__float_as_uint(val) << 32)
                            | (ull)(0xffffffffu - (unsigned)(flatbase + j));
                    if (key > bmin) {
                        best[0] = key;
                        #pragma unroll
                        for (int n = 0; n < KNB - 1; n++) {
                            ull x = best[n], y = best[n + 1];
                            ull lo = (x < y) ? x : y;
                            ull hi = (x < y) ? y : x;
                            best[n] = lo; best[n + 1] = hi;
                        }
                        bmin = best[0];
                    }
                }
            }
        }
        __syncwarp();
    }

    // ---- merge 256 per-thread top-20 lists -> global top-20 (descending) ----
    __syncthreads();
    ull* wred = (ull*)s_red;
    float* oSrc = out;
    float* oDst = out + S * KNB;        // 5120
    float* oW   = out + 2 * S * KNB;    // 10240

    for (int r = 0; r < KNB; r++) {
        ull m = 0ull;
        #pragma unroll
        for (int n = 0; n < KNB; n++) m = (best[n] > m) ? best[n] : m;
        #pragma unroll
        for (int o = 16; o > 0; o >>= 1) {
            ull other = __shfl_xor_sync(0xffffffffu, m, o);
            m = (other > m) ? other : m;
        }
        if (l == 0) wred[w] = m;
        __syncthreads();
        ull g = wred[0];
        #pragma unroll
        for (int q2 = 1; q2 < NWARPS; q2++) { ull o2 = wred[q2]; g = (o2 > g) ? o2 : g; }

        if (g != 0ull) {
            #pragma unroll
            for (int n = 0; n < KNB; n++) if (best[n] == g) best[n] = 0ull;  // unique owner
        }
        if (tid == 0) {
            int slot = b * KNB + r;
            if (g != 0ull) {
                float    val  = __uint_as_float((unsigned)(g >> 32));
                unsigned flat = 0xffffffffu - (unsigned)(g & 0xffffffffu);
                int ii = flat >> 8, jj = flat & 255;
                oSrc[slot] = (float)(b * S + ii);
                oDst[slot] = (float)(b * S + jj);
                oW[slot]   = val;
            } else {
                oSrc[slot] = 0.0f; oDst[slot] = 0.0f; oW[slot] = 0.0f;
            }
        }
        __syncthreads();
    }
}

extern "C" void kernel_launch(void* const* d_in, const int* in_sizes, int n_in,
                              void* d_out, int out_size)
{
    // metadata order: user_embeddings(unused), item_embeddings, timestamps,
    // interaction_weights, W1, b1, W2, b2, k_neighbors(=20, hardcoded)
    const float* item = (const float*)d_in[1];
    const float* tsg  = (const float*)d_in[2];
    const float* iwg  = (const float*)d_in[3];
    const float* W1   = (const float*)d_in[4];
    const float* b1   = (const float*)d_in[5];
    const float* W2   = (const float*)d_in[6];
    const float* b2   = (const float*)d_in[7];
    float* out = (float*)d_out;

    cudaFuncSetAttribute(ugc_kernel, cudaFuncAttributeMaxDynamicSharedMemorySize, SMEM_BYTES);
    ugc_kernel<<<S, NTHREADS, SMEM_BYTES>>>(item, tsg, iwg, W1, b1, W2, b2, out);
}